// round 12
// baseline (speedup 1.0000x reference)
#include <cuda_runtime.h>
#include <cuda_bf16.h>

// Problem constants (match reference_code)
#define B_DIM 4
#define L_DIM 4096
#define D_DIM 1024
#define NUM_KEEP 1024
#define NUM_DROP (L_DIM - NUM_KEEP)

// Output layout (flattened tuple, all float32):
//   [0)            outputs_dropped : B * NUM_KEEP * D   = 4,194,304
//   [OFF_MASKED)   outputs_masked  : B * L * D          = 16,777,216
//   [OFF_MASKDROP) mask_drop       : L                  = 4,096
//   [OFF_IDX)      idx_keep echo   : NUM_KEEP           = 1,024
#define OFF_MASKED   (B_DIM * NUM_KEEP * D_DIM)
#define OFF_MASKDROP (OFF_MASKED + B_DIM * L_DIM * D_DIM)
#define OFF_IDX      (OFF_MASKDROP + L_DIM)

#define ROWS_PER_BLOCK 8
#define MAIN_BLOCKS   ((B_DIM * L_DIM) / ROWS_PER_BLOCK)   // 2048
#define TAIL_BLOCKS   16
#define TOTAL_BLOCKS  (MAIN_BLOCKS + TAIL_BLOCKS)

// 32-byte opaque bundle: four b64 lanes. Data is never unpacked — loads and
// stores are both 256-bit with L2::evict_first (streaming policy; the .cs-like
// policy is what won R10 by eliminating the post-kernel dirty-L2 drain).
struct C256 { unsigned long long x0, x1, x2, x3; };

__device__ __forceinline__ C256 ld256_ef(const void* p) {
    C256 c;
    asm volatile("ld.global.L2::evict_first.v4.b64 {%0,%1,%2,%3}, [%4];"
                 : "=l"(c.x0), "=l"(c.x1), "=l"(c.x2), "=l"(c.x3) : "l"(p));
    return c;
}
__device__ __forceinline__ void st256_ef(void* p, C256 c) {
    asm volatile("st.global.L2::evict_first.v4.b64 [%0], {%1,%2,%3,%4};"
                 :: "l"(p), "l"(c.x0), "l"(c.x1), "l"(c.x2), "l"(c.x3) : "memory");
}

// lower_bound over sorted idx_keep in GLOBAL memory (tail blocks only).
__device__ __forceinline__ int lower_bound_g(const int* __restrict__ idx, int v) {
    int lo = 0, hi = NUM_KEEP;
    #pragma unroll
    for (int it = 0; it < 11; ++it) {
        if (lo < hi) {
            int mid = (lo + hi) >> 1;
            if (__ldg(&idx[mid]) < v) lo = mid + 1; else hi = mid;
        }
    }
    return lo;
}

__global__ void __launch_bounds__(256)
mask_fused_kernel(const float* __restrict__ inputs,
                  const float* __restrict__ mask_embedding,
                  const int4* __restrict__ idx_keep,
                  float* __restrict__ out) {
    __shared__ int s_flag[ROWS_PER_BLOCK];

    const int tid = threadIdx.x;   // 0..255
    const int bid = blockIdx.x;

    if (bid < MAIN_BLOCKS) {
        // ----- main path: 8 rows/block; 2 rows per slab pass, each thread
        //       owns one 32-byte chunk (c) of its row.
        const int row0 = bid * ROWS_PER_BLOCK;
        const int l0   = row0 & (L_DIM - 1);   // 8 rows never straddle a batch
        const int r2   = tid >> 7;     // 0..1  : row within slab
        const int c    = tid & 127;    // 0..127: 32B chunk within row

        if (tid < ROWS_PER_BLOCK) s_flag[tid] = 0;

        // Register scatter: each thread tests its 4 idx values (rank=4*tid+j)
        // against window [l0, l0+8). Unique values -> conflict-free.
        const int4 q = __ldg(&idx_keep[tid]);
        __syncthreads();
        {
            unsigned d;
            d = (unsigned)(q.x - l0); if (d < ROWS_PER_BLOCK) s_flag[d] = 4 * tid + 1;
            d = (unsigned)(q.y - l0); if (d < ROWS_PER_BLOCK) s_flag[d] = 4 * tid + 2;
            d = (unsigned)(q.z - l0); if (d < ROWS_PER_BLOCK) s_flag[d] = 4 * tid + 3;
            d = (unsigned)(q.w - l0); if (d < ROWS_PER_BLOCK) s_flag[d] = 4 * tid + 4;
        }
        __syncthreads();

        float* __restrict__ dropped = out;               // [B,K,D]
        float* __restrict__ masked  = out + OFF_MASKED;  // [B,L,D]

        // register-cached mask_embedding chunk (kept resident: plain __ldg)
        C256 me;
        {
            const unsigned long long* mep =
                (const unsigned long long*)(mask_embedding + c * 8);
            me.x0 = __ldg(&mep[0]); me.x1 = __ldg(&mep[1]);
            me.x2 = __ldg(&mep[2]); me.x3 = __ldg(&mep[3]);
        }

        int flags[4];
        #pragma unroll
        for (int p = 0; p < 4; ++p) flags[p] = s_flag[p * 2 + r2];

        // front-batch keep-row loads (up to 4 independent 256-bit loads)
        C256 v[4];
        #pragma unroll
        for (int p = 0; p < 4; ++p) {
            if (flags[p]) {
                const int row = row0 + p * 2 + r2;
                v[p] = ld256_ef(inputs + (size_t)row * D_DIM + c * 8);
            }
        }

        #pragma unroll
        for (int p = 0; p < 4; ++p) {
            const int row = row0 + p * 2 + r2;
            float* mrow = masked + (size_t)row * D_DIM + c * 8;
            if (flags[p]) {
                const int b = row >> 12;           // row / L_DIM
                const int k = flags[p] - 1;
                st256_ef(mrow, v[p]);
                st256_ef(dropped + ((size_t)b * NUM_KEEP + k) * D_DIM + c * 8, v[p]);
            } else {
                st256_ef(mrow, me);
            }
        }
    } else {
        // ----- tail path: mask_drop (4096 over 16 blocks) + idx echo
        const int* idx32 = (const int*)idx_keep;
        const int tb = bid - MAIN_BLOCKS;          // 0..15
        const int i  = tb * 256 + tid;             // 0..4095
        int pos = lower_bound_g(idx32, i);
        bool kept = (pos < NUM_KEEP && __ldg(&idx32[pos]) == i);
        out[OFF_MASKDROP + i] = kept ? 0.0f : 1.0f;
        if (tb < 4) {
            const int j = tb * 256 + tid;          // 0..1023
            out[OFF_IDX + j] = (float)__ldg(&idx32[j]);
        }
    }
}

// ---------------------------------------------------------------------------
extern "C" void kernel_launch(void* const* d_in, const int* in_sizes, int n_in,
                              void* d_out, int out_size) {
    const float* inputs         = (const float*)d_in[0];  // [B, L, D] f32
    const float* mask_embedding = (const float*)d_in[1];  // [D] f32
    const int4*  idx_keep       = (const int4*)d_in[2];   // [NUM_KEEP] i32
    float*       out            = (float*)d_out;

    mask_fused_kernel<<<TOTAL_BLOCKS, 256>>>(inputs, mask_embedding, idx_keep, out);
}